// round 1
// baseline (speedup 1.0000x reference)
#include <cuda_runtime.h>
#include <math.h>

#define B_ 64
#define T_ 1024
#define E_ 512
#define H_ 1024
#define V_ 512

// 256 MB scratch: holds xproj, then overwritten in-place with hidden states h_t.
__device__ float g_hs[(size_t)B_ * T_ * H_];
// Per-row-group barrier counters (4 independent row groups of 16 batch rows).
__device__ unsigned g_bar[4];

__global__ void zero_bar_kernel() {
    if (threadIdx.x < 4) g_bar[threadIdx.x] = 0u;
}

// ---------------------------------------------------------------------------
// Generic fp32 GEMM with bias: C[M,N] = A[M,K] @ B[K,N] + bias[N]
// 128x128 tile, K-step 8, 256 threads, 8x8 register micro-tile.
// ---------------------------------------------------------------------------
__global__ __launch_bounds__(256) void gemm_bias_kernel(
    const float* __restrict__ A, const float* __restrict__ Bm,
    const float* __restrict__ bias, float* __restrict__ C,
    int M, int N, int K)
{
    __shared__ float As[8][128];
    __shared__ float Bs[8][128];

    const int tid  = threadIdx.x;
    const int bx   = blockIdx.x * 128;
    const int by   = blockIdx.y * 128;
    const int arow = tid >> 1;
    const int acol = (tid & 1) << 2;
    const int brow = tid >> 5;
    const int bcol = (tid & 31) << 2;
    const int tx   = (tid & 15) << 3;
    const int ty   = (tid >> 4) << 3;

    float acc[8][8];
#pragma unroll
    for (int i = 0; i < 8; ++i)
#pragma unroll
        for (int j = 0; j < 8; ++j) acc[i][j] = 0.f;

    const float* Ap = A + (size_t)(by + arow) * K + acol;
    const float* Bp = Bm + (size_t)brow * N + (bx + bcol);

    for (int k0 = 0; k0 < K; k0 += 8) {
        float4 av = *(const float4*)(Ap + k0);
        float4 bv = *(const float4*)(Bp + (size_t)k0 * N);
        As[acol + 0][arow] = av.x;
        As[acol + 1][arow] = av.y;
        As[acol + 2][arow] = av.z;
        As[acol + 3][arow] = av.w;
        *(float4*)(&Bs[brow][bcol]) = bv;
        __syncthreads();
#pragma unroll
        for (int kk = 0; kk < 8; ++kk) {
            float a[8], b[8];
            *(float4*)(&a[0]) = *(const float4*)(&As[kk][ty]);
            *(float4*)(&a[4]) = *(const float4*)(&As[kk][ty + 4]);
            *(float4*)(&b[0]) = *(const float4*)(&Bs[kk][tx]);
            *(float4*)(&b[4]) = *(const float4*)(&Bs[kk][tx + 4]);
#pragma unroll
            for (int i = 0; i < 8; ++i)
#pragma unroll
                for (int j = 0; j < 8; ++j)
                    acc[i][j] = fmaf(a[i], b[j], acc[i][j]);
        }
        __syncthreads();
    }

    float bj[8];
#pragma unroll
    for (int j = 0; j < 8; ++j) bj[j] = bias[bx + tx + j];
#pragma unroll
    for (int i = 0; i < 8; ++i) {
        size_t row = (size_t)(by + ty + i);
        float4 v0 = make_float4(acc[i][0] + bj[0], acc[i][1] + bj[1],
                                acc[i][2] + bj[2], acc[i][3] + bj[3]);
        float4 v1 = make_float4(acc[i][4] + bj[4], acc[i][5] + bj[5],
                                acc[i][6] + bj[6], acc[i][7] + bj[7]);
        *(float4*)(&C[row * N + bx + tx])     = v0;
        *(float4*)(&C[row * N + bx + tx + 4]) = v1;
    }
}

// ---------------------------------------------------------------------------
// Persistent recurrence kernel: 128 CTAs = 4 row-groups x 32 column slices.
// W_hh slice [1024x32] resident in smem for all T steps; h slab staged per
// step from L2; per-row-group software barrier each step.
// ---------------------------------------------------------------------------
__global__ __launch_bounds__(256) void rnn_steps_kernel(const float* __restrict__ W_hh)
{
    extern __shared__ float sm[];
    float* Ws = sm;                 // [1024][32]
    float* Hs = sm + 1024 * 32;     // [16][1024]

    const int tid  = threadIdx.x;
    const int cc   = blockIdx.x & 31;
    const int rb   = blockIdx.x >> 5;
    const int n0   = cc * 32;
    const int b0   = rb * 16;
    const int lane = tid & 31;
    const int warp = tid >> 5;
    const int r0   = warp * 2;
    const int r1   = warp * 2 + 1;

    for (int idx = tid; idx < 1024 * 32; idx += 256) {
        int k = idx >> 5, c = idx & 31;
        Ws[idx] = W_hh[(size_t)k * H_ + n0 + c];
    }

    volatile unsigned* barp = (volatile unsigned*)&g_bar[rb];

    for (int t = 0; t < T_; ++t) {
        __syncthreads();
        if (t == 0) {
            for (int idx = tid; idx < 16 * 1024; idx += 256) Hs[idx] = 0.f;
        } else {
            for (int idx = tid; idx < 16 * 256; idx += 256) {
                int r  = idx >> 8;
                int c4 = idx & 255;
                const float4* p =
                    (const float4*)(g_hs + ((size_t)(b0 + r) * T_ + (t - 1)) * H_) + c4;
                ((float4*)(Hs + r * 1024))[c4] = __ldcg(p);
            }
        }
        __syncthreads();

        float acc0 = 0.f, acc1 = 0.f;
        const float4* h0 = (const float4*)(Hs + r0 * 1024);
        const float4* h1 = (const float4*)(Hs + r1 * 1024);
#pragma unroll 8
        for (int k4 = 0; k4 < 256; ++k4) {
            float4 a0 = h0[k4];
            float4 a1 = h1[k4];
            int kb = (k4 << 7) + lane;
            float w0 = Ws[kb];
            float w1 = Ws[kb + 32];
            float w2 = Ws[kb + 64];
            float w3 = Ws[kb + 96];
            acc0 = fmaf(a0.x, w0, acc0);
            acc1 = fmaf(a1.x, w0, acc1);
            acc0 = fmaf(a0.y, w1, acc0);
            acc1 = fmaf(a1.y, w1, acc1);
            acc0 = fmaf(a0.z, w2, acc0);
            acc1 = fmaf(a1.z, w2, acc1);
            acc0 = fmaf(a0.w, w3, acc0);
            acc1 = fmaf(a1.w, w3, acc1);
        }

        size_t i0 = ((size_t)(b0 + r0) * T_ + t) * H_ + n0 + lane;
        size_t i1 = ((size_t)(b0 + r1) * T_ + t) * H_ + n0 + lane;
        float o0 = tanhf(acc0 + __ldcg(g_hs + i0));
        float o1 = tanhf(acc1 + __ldcg(g_hs + i1));
        g_hs[i0] = o0;
        g_hs[i1] = o1;

        __threadfence();
        __syncthreads();
        if (tid == 0) {
            atomicAdd(&g_bar[rb], 1u);
            unsigned target = 32u * (unsigned)(t + 1);
            while (*barp < target) { }
        }
        __syncthreads();
    }
}

__global__ void hfinal_kernel(float* __restrict__ out)
{
    int idx = blockIdx.x * blockDim.x + threadIdx.x;
    if (idx < B_ * H_) {
        int b = idx >> 10;
        int j = idx & 1023;
        out[idx] = g_hs[((size_t)b * T_ + (T_ - 1)) * H_ + j];
    }
}

extern "C" void kernel_launch(void* const* d_in, const int* in_sizes, int n_in,
                              void* d_out, int out_size)
{
    const float* X    = (const float*)d_in[0];
    const float* W_xh = (const float*)d_in[1];
    const float* b_h  = (const float*)d_in[2];
    const float* W_hh = (const float*)d_in[3];
    const float* W_hy = (const float*)d_in[4];
    const float* b_y  = (const float*)d_in[5];
    float* out = (float*)d_out;

    float* hs_ptr = nullptr;
    cudaGetSymbolAddress((void**)&hs_ptr, g_hs);

    cudaFuncSetAttribute(rnn_steps_kernel,
                         cudaFuncAttributeMaxDynamicSharedMemorySize, 196608);

    zero_bar_kernel<<<1, 32>>>();

    {   // xproj = X @ W_xh + b_h  (M=65536, N=1024, K=512) -> g_hs
        dim3 grid(H_ / 128, (B_ * T_) / 128);
        gemm_bias_kernel<<<grid, 256>>>(X, W_xh, b_h, hs_ptr, B_ * T_, H_, E_);
    }

    rnn_steps_kernel<<<128, 256, 196608>>>(W_hh);

    hfinal_kernel<<<(B_ * H_) / 256, 256>>>(out + (size_t)B_ * T_ * V_);

    {   // Y = hs @ W_hy + b_y  (M=65536, N=512, K=1024) -> out
        dim3 grid(V_ / 128, (B_ * T_) / 128);
        gemm_bias_kernel<<<grid, 256>>>(hs_ptr, W_hy, b_y, out, B_ * T_, V_, H_);
    }
}

// round 2
// speedup vs baseline: 1.0248x; 1.0248x over previous
#include <cuda_runtime.h>
#include <math.h>

#define B_ 64
#define T_ 1024
#define E_ 512
#define H_ 1024
#define V_ 512

// 256 MB scratch: holds xproj, then overwritten in-place with hidden states h_t.
__device__ float g_hs[(size_t)B_ * T_ * H_];
// Per-row-group barrier counters (4 independent row groups of 16 batch rows).
__device__ unsigned g_bar[4];

__global__ void zero_bar_kernel() {
    if (threadIdx.x < 4) g_bar[threadIdx.x] = 0u;
}

// ---------------------------------------------------------------------------
// TF32 helpers
// ---------------------------------------------------------------------------
__device__ __forceinline__ unsigned f2tf(float x) {
    unsigned u;
    asm("cvt.rna.tf32.f32 %0, %1;" : "=r"(u) : "f"(x));
    return u;
}
__device__ __forceinline__ void split_tf32(float x, unsigned& hi, unsigned& lo) {
    hi = f2tf(x);
    float l = x - __uint_as_float(hi);
    lo = f2tf(l);
}
__device__ __forceinline__ void mma_tf32(float acc[4], unsigned a0, unsigned a1,
                                         unsigned a2, unsigned a3,
                                         unsigned b0, unsigned b1) {
    asm volatile(
        "mma.sync.aligned.m16n8k8.row.col.f32.tf32.tf32.f32 "
        "{%0,%1,%2,%3}, {%4,%5,%6,%7}, {%8,%9}, {%0,%1,%2,%3};"
        : "+f"(acc[0]), "+f"(acc[1]), "+f"(acc[2]), "+f"(acc[3])
        : "r"(a0), "r"(a1), "r"(a2), "r"(a3), "r"(b0), "r"(b1));
}

// ---------------------------------------------------------------------------
// 3xTF32 GEMM with bias: C[M,N] = A[M,K] @ B[K,N] + bias[N]
// CTA tile 128x128, k-step 16, 256 threads, 8 warps each computing 64x32
// via m16n8k8 tf32 MMA. Triple-buffered cp.async pipeline.
// A smem stride 20 floats ([m][k] layout), B smem stride 136 ([k][n]) —
// both conflict-free for the mma fragment access patterns.
// Requires M%128==0, N%128==0, K%16==0 (true for all shapes here).
// ---------------------------------------------------------------------------
#define GSTAGE 4736   // floats per pipeline stage: A 128*20 + B 16*136

__global__ __launch_bounds__(256) void gemm_tf32_kernel(
    const float* __restrict__ A, const float* __restrict__ Bm,
    const float* __restrict__ bias, float* __restrict__ C,
    int M, int N, int K)
{
    extern __shared__ float smem[];
    const int tid  = threadIdx.x;
    const int lane = tid & 31;
    const int warp = tid >> 5;
    const int wm   = warp & 1;        // 2 warp-rows
    const int wn   = warp >> 1;       // 4 warp-cols
    const int g    = lane >> 2;
    const int t    = lane & 3;
    const int bx   = blockIdx.x;      // N tile
    const int by   = blockIdx.y;      // M tile

    const int KT = K >> 4;

    // stage loader: A tile 128x16 -> As[m][k] (stride 20); B tile 16x128 -> Bs[k][n] (stride 136)
    auto load_stage = [&](int s, int kt) {
        float* As = smem + s * GSTAGE;
        float* Bs = As + 2560;
        const int k0 = kt << 4;
#pragma unroll
        for (int i = 0; i < 2; ++i) {
            int c  = tid + i * 256;          // 0..511
            int m  = c >> 2;
            int kq = (c & 3) << 2;
            const float* src = A + (size_t)(by * 128 + m) * K + k0 + kq;
            unsigned dst = (unsigned)__cvta_generic_to_shared(As + m * 20 + kq);
            asm volatile("cp.async.cg.shared.global [%0], [%1], 16;"
                         :: "r"(dst), "l"(src));
        }
#pragma unroll
        for (int i = 0; i < 2; ++i) {
            int c  = tid + i * 256;
            int k  = c >> 5;
            int nq = (c & 31) << 2;
            const float* src = Bm + (size_t)(k0 + k) * N + bx * 128 + nq;
            unsigned dst = (unsigned)__cvta_generic_to_shared(Bs + k * 136 + nq);
            asm volatile("cp.async.cg.shared.global [%0], [%1], 16;"
                         :: "r"(dst), "l"(src));
        }
    };

    float acc[4][4][4];
#pragma unroll
    for (int i = 0; i < 4; ++i)
#pragma unroll
        for (int j = 0; j < 4; ++j)
#pragma unroll
            for (int r = 0; r < 4; ++r) acc[i][j][r] = 0.f;

    load_stage(0, 0);
    asm volatile("cp.async.commit_group;");
    load_stage(1, 1);
    asm volatile("cp.async.commit_group;");

    for (int kt = 0; kt < KT; ++kt) {
        asm volatile("cp.async.wait_group 1;");
        __syncthreads();
        if (kt + 2 < KT) load_stage((kt + 2) % 3, kt + 2);
        asm volatile("cp.async.commit_group;");

        const float* As = smem + (kt % 3) * GSTAGE;
        const float* Bs = As + 2560;

#pragma unroll
        for (int k8 = 0; k8 < 2; ++k8) {
            unsigned ahi[4][4], alo[4][4], bhi[4][2], blo[4][2];
            const int kk = (k8 << 3) + t;
#pragma unroll
            for (int mt = 0; mt < 4; ++mt) {
                int r = wm * 64 + mt * 16 + g;
                float v0 = As[r * 20 + kk];
                float v1 = As[(r + 8) * 20 + kk];
                float v2 = As[r * 20 + kk + 4];
                float v3 = As[(r + 8) * 20 + kk + 4];
                split_tf32(v0, ahi[mt][0], alo[mt][0]);
                split_tf32(v1, ahi[mt][1], alo[mt][1]);
                split_tf32(v2, ahi[mt][2], alo[mt][2]);
                split_tf32(v3, ahi[mt][3], alo[mt][3]);
            }
#pragma unroll
            for (int nt = 0; nt < 4; ++nt) {
                int cidx = wn * 32 + nt * 8 + g;
                float v0 = Bs[kk * 136 + cidx];
                float v1 = Bs[(kk + 4) * 136 + cidx];
                split_tf32(v0, bhi[nt][0], blo[nt][0]);
                split_tf32(v1, bhi[nt][1], blo[nt][1]);
            }
#pragma unroll
            for (int mt = 0; mt < 4; ++mt)
#pragma unroll
                for (int nt = 0; nt < 4; ++nt) {
                    mma_tf32(acc[mt][nt], ahi[mt][0], ahi[mt][1], ahi[mt][2],
                             ahi[mt][3], bhi[nt][0], bhi[nt][1]);
                    mma_tf32(acc[mt][nt], ahi[mt][0], ahi[mt][1], ahi[mt][2],
                             ahi[mt][3], blo[nt][0], blo[nt][1]);
                    mma_tf32(acc[mt][nt], alo[mt][0], alo[mt][1], alo[mt][2],
                             alo[mt][3], bhi[nt][0], bhi[nt][1]);
                }
        }
    }

    // Epilogue: bias add + fp32 store. c0,c1 -> (row, 2t..2t+1); c2,c3 -> row+8.
#pragma unroll
    for (int mt = 0; mt < 4; ++mt) {
        int row0 = by * 128 + wm * 64 + mt * 16 + g;
#pragma unroll
        for (int nt = 0; nt < 4; ++nt) {
            int col = bx * 128 + wn * 32 + nt * 8 + 2 * t;
            float b0 = bias[col];
            float b1 = bias[col + 1];
            float2 v0 = make_float2(acc[mt][nt][0] + b0, acc[mt][nt][1] + b1);
            float2 v1 = make_float2(acc[mt][nt][2] + b0, acc[mt][nt][3] + b1);
            *(float2*)(&C[(size_t)row0 * N + col])       = v0;
            *(float2*)(&C[(size_t)(row0 + 8) * N + col]) = v1;
        }
    }
}

// ---------------------------------------------------------------------------
// Persistent recurrence kernel: 128 CTAs = 4 row-groups x 32 column slices.
// W_hh slice [1024x32] resident in smem for all T steps; h slab staged per
// step from L2; per-row-group software barrier each step. (Unchanged R1.)
// ---------------------------------------------------------------------------
__global__ __launch_bounds__(256) void rnn_steps_kernel(const float* __restrict__ W_hh)
{
    extern __shared__ float sm[];
    float* Ws = sm;                 // [1024][32]
    float* Hs = sm + 1024 * 32;     // [16][1024]

    const int tid  = threadIdx.x;
    const int cc   = blockIdx.x & 31;
    const int rb   = blockIdx.x >> 5;
    const int n0   = cc * 32;
    const int b0   = rb * 16;
    const int lane = tid & 31;
    const int warp = tid >> 5;
    const int r0   = warp * 2;
    const int r1   = warp * 2 + 1;

    for (int idx = tid; idx < 1024 * 32; idx += 256) {
        int k = idx >> 5, c = idx & 31;
        Ws[idx] = W_hh[(size_t)k * H_ + n0 + c];
    }

    volatile unsigned* barp = (volatile unsigned*)&g_bar[rb];

    for (int t = 0; t < T_; ++t) {
        __syncthreads();
        if (t == 0) {
            for (int idx = tid; idx < 16 * 1024; idx += 256) Hs[idx] = 0.f;
        } else {
            for (int idx = tid; idx < 16 * 256; idx += 256) {
                int r  = idx >> 8;
                int c4 = idx & 255;
                const float4* p =
                    (const float4*)(g_hs + ((size_t)(b0 + r) * T_ + (t - 1)) * H_) + c4;
                ((float4*)(Hs + r * 1024))[c4] = __ldcg(p);
            }
        }
        __syncthreads();

        float acc0 = 0.f, acc1 = 0.f;
        const float4* h0 = (const float4*)(Hs + r0 * 1024);
        const float4* h1 = (const float4*)(Hs + r1 * 1024);
#pragma unroll 8
        for (int k4 = 0; k4 < 256; ++k4) {
            float4 a0 = h0[k4];
            float4 a1 = h1[k4];
            int kb = (k4 << 7) + lane;
            float w0 = Ws[kb];
            float w1 = Ws[kb + 32];
            float w2 = Ws[kb + 64];
            float w3 = Ws[kb + 96];
            acc0 = fmaf(a0.x, w0, acc0);
            acc1 = fmaf(a1.x, w0, acc1);
            acc0 = fmaf(a0.y, w1, acc0);
            acc1 = fmaf(a1.y, w1, acc1);
            acc0 = fmaf(a0.z, w2, acc0);
            acc1 = fmaf(a1.z, w2, acc1);
            acc0 = fmaf(a0.w, w3, acc0);
            acc1 = fmaf(a1.w, w3, acc1);
        }

        size_t i0 = ((size_t)(b0 + r0) * T_ + t) * H_ + n0 + lane;
        size_t i1 = ((size_t)(b0 + r1) * T_ + t) * H_ + n0 + lane;
        float o0 = tanhf(acc0 + __ldcg(g_hs + i0));
        float o1 = tanhf(acc1 + __ldcg(g_hs + i1));
        g_hs[i0] = o0;
        g_hs[i1] = o1;

        __threadfence();
        __syncthreads();
        if (tid == 0) {
            atomicAdd(&g_bar[rb], 1u);
            unsigned target = 32u * (unsigned)(t + 1);
            while (*barp < target) { }
        }
        __syncthreads();
    }
}

__global__ void hfinal_kernel(float* __restrict__ out)
{
    int idx = blockIdx.x * blockDim.x + threadIdx.x;
    if (idx < B_ * H_) {
        int b = idx >> 10;
        int j = idx & 1023;
        out[idx] = g_hs[((size_t)b * T_ + (T_ - 1)) * H_ + j];
    }
}

extern "C" void kernel_launch(void* const* d_in, const int* in_sizes, int n_in,
                              void* d_out, int out_size)
{
    const float* X    = (const float*)d_in[0];
    const float* W_xh = (const float*)d_in[1];
    const float* b_h  = (const float*)d_in[2];
    const float* W_hh = (const float*)d_in[3];
    const float* W_hy = (const float*)d_in[4];
    const float* b_y  = (const float*)d_in[5];
    float* out = (float*)d_out;

    float* hs_ptr = nullptr;
    cudaGetSymbolAddress((void**)&hs_ptr, g_hs);

    cudaFuncSetAttribute(rnn_steps_kernel,
                         cudaFuncAttributeMaxDynamicSharedMemorySize, 196608);
    cudaFuncSetAttribute(gemm_tf32_kernel,
                         cudaFuncAttributeMaxDynamicSharedMemorySize, GSTAGE * 3 * 4);

    zero_bar_kernel<<<1, 32>>>();

    {   // xproj = X @ W_xh + b_h  (M=65536, N=1024, K=512) -> g_hs
        dim3 grid(H_ / 128, (B_ * T_) / 128);
        gemm_tf32_kernel<<<grid, 256, GSTAGE * 3 * 4>>>(X, W_xh, b_h, hs_ptr,
                                                        B_ * T_, H_, E_);
    }

    rnn_steps_kernel<<<128, 256, 196608>>>(W_hh);

    hfinal_kernel<<<(B_ * H_) / 256, 256>>>(out + (size_t)B_ * T_ * V_);

    {   // Y = hs @ W_hy + b_y  (M=65536, N=512, K=1024) -> out
        dim3 grid(V_ / 128, (B_ * T_) / 128);
        gemm_tf32_kernel<<<grid, 256, GSTAGE * 3 * 4>>>(hs_ptr, W_hy, b_y, out,
                                                        B_ * T_, V_, H_);
    }
}

// round 3
// speedup vs baseline: 2.1750x; 2.1222x over previous
#include <cuda_runtime.h>
#include <cuda_bf16.h>
#include <math.h>

#define B_ 64
#define T_ 1024
#define E_ 512
#define H_ 1024
#define V_ 512

// 256 MB scratch: holds xproj, then overwritten in-place with hidden states h_t.
__device__ float g_hs[(size_t)B_ * T_ * H_];
// Ping-pong pre-split hidden state (bf16 hi/lo), written by step t, read by t+1.
__device__ __nv_bfloat16 g_hhi[2 * B_ * H_];
__device__ __nv_bfloat16 g_hlo[2 * B_ * H_];
// Per-row-group barrier counters (4 independent row groups of 16 batch rows).
__device__ unsigned g_bar[4];

// ---------------------------------------------------------------------------
// TF32 helpers (GEMM path)
// ---------------------------------------------------------------------------
__device__ __forceinline__ unsigned f2tf(float x) {
    unsigned u;
    asm("cvt.rna.tf32.f32 %0, %1;" : "=r"(u) : "f"(x));
    return u;
}
__device__ __forceinline__ void split_tf32(float x, unsigned& hi, unsigned& lo) {
    hi = f2tf(x);
    float l = x - __uint_as_float(hi);
    lo = f2tf(l);
}
__device__ __forceinline__ void mma_tf32(float acc[4], unsigned a0, unsigned a1,
                                         unsigned a2, unsigned a3,
                                         unsigned b0, unsigned b1) {
    asm volatile(
        "mma.sync.aligned.m16n8k8.row.col.f32.tf32.tf32.f32 "
        "{%0,%1,%2,%3}, {%4,%5,%6,%7}, {%8,%9}, {%0,%1,%2,%3};"
        : "+f"(acc[0]), "+f"(acc[1]), "+f"(acc[2]), "+f"(acc[3])
        : "r"(a0), "r"(a1), "r"(a2), "r"(a3), "r"(b0), "r"(b1));
}

// bf16 MMA helpers (recurrence path)
#define LDSM4(r0, r1, r2, r3, addr)                                          \
    asm volatile("ldmatrix.sync.aligned.m8n8.x4.shared.b16 {%0,%1,%2,%3}, [%4];" \
                 : "=r"(r0), "=r"(r1), "=r"(r2), "=r"(r3) : "r"(addr))

#define MMA_BF16(d, a0, a1, a2, a3, b0, b1)                                  \
    asm volatile("mma.sync.aligned.m16n8k16.row.col.f32.bf16.bf16.f32 "     \
                 "{%0,%1,%2,%3},{%4,%5,%6,%7},{%8,%9},{%0,%1,%2,%3};"       \
                 : "+f"(d[0]), "+f"(d[1]), "+f"(d[2]), "+f"(d[3])            \
                 : "r"(a0), "r"(a1), "r"(a2), "r"(a3), "r"(b0), "r"(b1))

// ---------------------------------------------------------------------------
// 3xTF32 GEMM with bias: C[M,N] = A[M,K] @ B[K,N] + bias[N]   (unchanged R2)
// ---------------------------------------------------------------------------
#define GSTAGE 4736

__global__ __launch_bounds__(256) void gemm_tf32_kernel(
    const float* __restrict__ A, const float* __restrict__ Bm,
    const float* __restrict__ bias, float* __restrict__ C,
    int M, int N, int K, int zero_flag)
{
    extern __shared__ float smem[];
    const int tid  = threadIdx.x;
    const int lane = tid & 31;
    const int warp = tid >> 5;
    const int wm   = warp & 1;
    const int wn   = warp >> 1;
    const int g    = lane >> 2;
    const int t    = lane & 3;
    const int bx   = blockIdx.x;
    const int by   = blockIdx.y;

    if (zero_flag && bx == 0 && by == 0 && tid < 4) g_bar[tid] = 0u;

    const int KT = K >> 4;

    auto load_stage = [&](int s, int kt) {
        float* As = smem + s * GSTAGE;
        float* Bs = As + 2560;
        const int k0 = kt << 4;
#pragma unroll
        for (int i = 0; i < 2; ++i) {
            int c  = tid + i * 256;
            int m  = c >> 2;
            int kq = (c & 3) << 2;
            const float* src = A + (size_t)(by * 128 + m) * K + k0 + kq;
            unsigned dst = (unsigned)__cvta_generic_to_shared(As + m * 20 + kq);
            asm volatile("cp.async.cg.shared.global [%0], [%1], 16;"
                         :: "r"(dst), "l"(src));
        }
#pragma unroll
        for (int i = 0; i < 2; ++i) {
            int c  = tid + i * 256;
            int k  = c >> 5;
            int nq = (c & 31) << 2;
            const float* src = Bm + (size_t)(k0 + k) * N + bx * 128 + nq;
            unsigned dst = (unsigned)__cvta_generic_to_shared(Bs + k * 136 + nq);
            asm volatile("cp.async.cg.shared.global [%0], [%1], 16;"
                         :: "r"(dst), "l"(src));
        }
    };

    float acc[4][4][4];
#pragma unroll
    for (int i = 0; i < 4; ++i)
#pragma unroll
        for (int j = 0; j < 4; ++j)
#pragma unroll
            for (int r = 0; r < 4; ++r) acc[i][j][r] = 0.f;

    load_stage(0, 0);
    asm volatile("cp.async.commit_group;");
    load_stage(1, 1);
    asm volatile("cp.async.commit_group;");

    for (int kt = 0; kt < KT; ++kt) {
        asm volatile("cp.async.wait_group 1;");
        __syncthreads();
        if (kt + 2 < KT) load_stage((kt + 2) % 3, kt + 2);
        asm volatile("cp.async.commit_group;");

        const float* As = smem + (kt % 3) * GSTAGE;
        const float* Bs = As + 2560;

#pragma unroll
        for (int k8 = 0; k8 < 2; ++k8) {
            unsigned ahi[4][4], alo[4][4], bhi[4][2], blo[4][2];
            const int kk = (k8 << 3) + t;
#pragma unroll
            for (int mt = 0; mt < 4; ++mt) {
                int r = wm * 64 + mt * 16 + g;
                split_tf32(As[r * 20 + kk],        ahi[mt][0], alo[mt][0]);
                split_tf32(As[(r + 8) * 20 + kk],  ahi[mt][1], alo[mt][1]);
                split_tf32(As[r * 20 + kk + 4],    ahi[mt][2], alo[mt][2]);
                split_tf32(As[(r + 8) * 20 + kk + 4], ahi[mt][3], alo[mt][3]);
            }
#pragma unroll
            for (int nt = 0; nt < 4; ++nt) {
                int cidx = wn * 32 + nt * 8 + g;
                split_tf32(Bs[kk * 136 + cidx],       bhi[nt][0], blo[nt][0]);
                split_tf32(Bs[(kk + 4) * 136 + cidx], bhi[nt][1], blo[nt][1]);
            }
#pragma unroll
            for (int mt = 0; mt < 4; ++mt)
#pragma unroll
                for (int nt = 0; nt < 4; ++nt) {
                    mma_tf32(acc[mt][nt], ahi[mt][0], ahi[mt][1], ahi[mt][2],
                             ahi[mt][3], bhi[nt][0], bhi[nt][1]);
                    mma_tf32(acc[mt][nt], ahi[mt][0], ahi[mt][1], ahi[mt][2],
                             ahi[mt][3], blo[nt][0], blo[nt][1]);
                    mma_tf32(acc[mt][nt], alo[mt][0], alo[mt][1], alo[mt][2],
                             alo[mt][3], bhi[nt][0], bhi[nt][1]);
                }
        }
    }

#pragma unroll
    for (int mt = 0; mt < 4; ++mt) {
        int row0 = by * 128 + wm * 64 + mt * 16 + g;
#pragma unroll
        for (int nt = 0; nt < 4; ++nt) {
            int col = bx * 128 + wn * 32 + nt * 8 + 2 * t;
            float b0 = bias[col];
            float b1 = bias[col + 1];
            float2 v0 = make_float2(acc[mt][nt][0] + b0, acc[mt][nt][1] + b1);
            float2 v1 = make_float2(acc[mt][nt][2] + b0, acc[mt][nt][3] + b1);
            *(float2*)(&C[(size_t)row0 * N + col])       = v0;
            *(float2*)(&C[(size_t)(row0 + 8) * N + col]) = v1;
        }
    }
}

// ---------------------------------------------------------------------------
// Persistent recurrence kernel, bf16 3-term HMMA version.
// 128 CTAs = 4 row-groups (16 batch rows) x 32 column slices (32 H-cols).
// W_hh slice pre-split ONCE to bf16 hi/lo, stored [n][k] stride 1032 in smem.
// h_{t-1} staged per step as pre-split bf16 (written by step t-1 writers) into
// smem [16][1032] hi/lo; each warp: 1 n-tile(8) x K-half(512), 3 acc chains.
// ---------------------------------------------------------------------------
__global__ __launch_bounds__(256) void rnn_steps_kernel(
    const float* __restrict__ W_hh, float* __restrict__ out_hf)
{
    extern __shared__ char smc[];
    __nv_bfloat16* Whi = (__nv_bfloat16*)smc;          // [32][1032]
    __nv_bfloat16* Wlo = Whi + 32 * 1032;
    __nv_bfloat16* Hhi = Wlo + 32 * 1032;              // [16][1032]
    __nv_bfloat16* Hlo = Hhi + 16 * 1032;
    float*         red = (float*)(Hlo + 16 * 1032);    // [16][32]

    const int tid  = threadIdx.x;
    const int lane = tid & 31;
    const int warp = tid >> 5;
    const int cc   = blockIdx.x & 31;
    const int rb   = blockIdx.x >> 5;
    const int n0   = cc * 32;
    const int b0   = rb * 16;
    const int g    = lane >> 2;
    const int tq   = lane & 3;
    const int ntile = warp & 3;
    const int khalf = (warp >> 2) << 9;       // 0 or 512
    const int col   = ntile * 8 + 2 * tq;     // local output col (warps 0-3)

    // --- one-time: split + transpose W_hh slice into smem ---
    for (int idx = tid; idx < 32768; idx += 256) {
        int n = idx & 31, k = idx >> 5;
        float w = W_hh[(size_t)k * H_ + n0 + n];
        __nv_bfloat16 hi = __float2bfloat16(w);
        float lo = w - __bfloat162float(hi);
        Whi[n * 1032 + k] = hi;
        Wlo[n * 1032 + k] = __float2bfloat16(lo);
    }

    // ldmatrix lane addresses (A-frags), advance 32B per k16 chunk
    const int sub  = lane >> 3;
    const int lrow = ((sub & 1) << 3) + (lane & 7);
    const int lkof = (sub >> 1) << 3;
    unsigned abase_hi = (unsigned)__cvta_generic_to_shared(
        Hhi + lrow * 1032 + khalf + lkof);
    unsigned abase_lo = (unsigned)__cvta_generic_to_shared(
        Hlo + lrow * 1032 + khalf + lkof);

    const unsigned* bhiw = (const unsigned*)(Whi + (size_t)(ntile * 8 + g) * 1032);
    const unsigned* blow = (const unsigned*)(Wlo + (size_t)(ntile * 8 + g) * 1032);

    volatile unsigned* barp = (volatile unsigned*)&g_bar[rb];
    __syncthreads();   // Whi/Wlo ready

    for (int t = 0; t < T_; ++t) {
        // xp prefetch for the output-owning warps (row g and g+8, cols col..col+1)
        float2 xp0, xp1;
        size_t xbase0 = ((size_t)(b0 + g) * T_ + t) * H_ + n0 + col;
        size_t xbase1 = xbase0 + (size_t)8 * T_ * H_;
        if (warp < 4) {
            xp0 = __ldcg((const float2*)(g_hs + xbase0));
            xp1 = __ldcg((const float2*)(g_hs + xbase1));
        }

        float v00, v01, v10, v11;
        if (t > 0) {
            // stage pre-split h_{t-1} (bf16) into smem
            const int buf = (t - 1) & 1;
            const __nv_bfloat16* shh = g_hhi + ((size_t)buf * B_ + b0) * H_;
            const __nv_bfloat16* shl = g_hlo + ((size_t)buf * B_ + b0) * H_;
#pragma unroll
            for (int j = 0; j < 8; ++j) {
                int idx = j * 256 + tid;          // 0..2047 chunks of 8 halves
                int r = idx >> 7;
                int c = (idx & 127) << 3;
                *(uint4*)(Hhi + r * 1032 + c) =
                    __ldcg((const uint4*)(shh + r * H_ + c));
                *(uint4*)(Hlo + r * 1032 + c) =
                    __ldcg((const uint4*)(shl + r * H_ + c));
            }
            __syncthreads();

            float hh[4] = {0.f, 0.f, 0.f, 0.f};
            float hl[4] = {0.f, 0.f, 0.f, 0.f};
            float lh[4] = {0.f, 0.f, 0.f, 0.f};
            unsigned ah = abase_hi, al = abase_lo;
#pragma unroll 4
            for (int c = 0; c < 32; ++c) {
                unsigned a0, a1, a2, a3, l0, l1, l2, l3;
                LDSM4(a0, a1, a2, a3, ah);
                LDSM4(l0, l1, l2, l3, al);
                ah += 32; al += 32;
                int widx = ((khalf + (c << 4)) >> 1) + tq;
                unsigned bh0 = bhiw[widx], bh1 = bhiw[widx + 4];
                unsigned bl0 = blow[widx], bl1 = blow[widx + 4];
                MMA_BF16(hh, a0, a1, a2, a3, bh0, bh1);
                MMA_BF16(hl, a0, a1, a2, a3, bl0, bl1);
                MMA_BF16(lh, l0, l1, l2, l3, bh0, bh1);
            }
            float s0 = hh[0] + hl[0] + lh[0];
            float s1 = hh[1] + hl[1] + lh[1];
            float s2 = hh[2] + hl[2] + lh[2];
            float s3 = hh[3] + hl[3] + lh[3];
            if (warp >= 4) {
                *(float2*)(red + g * 32 + col)       = make_float2(s0, s1);
                *(float2*)(red + (g + 8) * 32 + col) = make_float2(s2, s3);
            }
            __syncthreads();
            if (warp < 4) {
                float2 r0 = *(float2*)(red + g * 32 + col);
                float2 r1 = *(float2*)(red + (g + 8) * 32 + col);
                v00 = s0 + r0.x + xp0.x;
                v01 = s1 + r0.y + xp0.y;
                v10 = s2 + r1.x + xp1.x;
                v11 = s3 + r1.y + xp1.y;
            }
        } else {
            if (warp < 4) {
                v00 = xp0.x; v01 = xp0.y; v10 = xp1.x; v11 = xp1.y;
            }
        }

        if (warp < 4) {
            float o00 = tanhf(v00), o01 = tanhf(v01);
            float o10 = tanhf(v10), o11 = tanhf(v11);
            *(float2*)(g_hs + xbase0) = make_float2(o00, o01);
            *(float2*)(g_hs + xbase1) = make_float2(o10, o11);

            // pre-split writes for next step's staging
            const int ob = t & 1;
            __nv_bfloat16 h00 = __float2bfloat16(o00);
            __nv_bfloat16 h01 = __float2bfloat16(o01);
            __nv_bfloat16 h10 = __float2bfloat16(o10);
            __nv_bfloat16 h11 = __float2bfloat16(o11);
            __nv_bfloat162 phi0; phi0.x = h00; phi0.y = h01;
            __nv_bfloat162 phi1; phi1.x = h10; phi1.y = h11;
            __nv_bfloat162 plo0;
            plo0.x = __float2bfloat16(o00 - __bfloat162float(h00));
            plo0.y = __float2bfloat16(o01 - __bfloat162float(h01));
            __nv_bfloat162 plo1;
            plo1.x = __float2bfloat16(o10 - __bfloat162float(h10));
            plo1.y = __float2bfloat16(o11 - __bfloat162float(h11));
            size_t d0 = ((size_t)ob * B_ + b0 + g) * H_ + n0 + col;
            size_t d1 = d0 + (size_t)8 * H_;
            *(__nv_bfloat162*)(g_hhi + d0) = phi0;
            *(__nv_bfloat162*)(g_hhi + d1) = phi1;
            *(__nv_bfloat162*)(g_hlo + d0) = plo0;
            *(__nv_bfloat162*)(g_hlo + d1) = plo1;

            if (t == T_ - 1) {
                size_t f0 = (size_t)(b0 + g) * H_ + n0 + col;
                *(float2*)(out_hf + f0)                 = make_float2(o00, o01);
                *(float2*)(out_hf + f0 + (size_t)8 * H_) = make_float2(o10, o11);
            }
        }

        __threadfence();
        __syncthreads();
        if (tid == 0) {
            atomicAdd(&g_bar[rb], 1u);
            unsigned target = 32u * (unsigned)(t + 1);
            while (*barp < target) { }
        }
        __syncthreads();
    }
}

extern "C" void kernel_launch(void* const* d_in, const int* in_sizes, int n_in,
                              void* d_out, int out_size)
{
    const float* X    = (const float*)d_in[0];
    const float* W_xh = (const float*)d_in[1];
    const float* b_h  = (const float*)d_in[2];
    const float* W_hh = (const float*)d_in[3];
    const float* W_hy = (const float*)d_in[4];
    const float* b_y  = (const float*)d_in[5];
    float* out = (float*)d_out;

    float* hs_ptr = nullptr;
    cudaGetSymbolAddress((void**)&hs_ptr, g_hs);

    cudaFuncSetAttribute(rnn_steps_kernel,
                         cudaFuncAttributeMaxDynamicSharedMemorySize, 200192);
    cudaFuncSetAttribute(gemm_tf32_kernel,
                         cudaFuncAttributeMaxDynamicSharedMemorySize, GSTAGE * 3 * 4);

    {   // xproj = X @ W_xh + b_h  (M=65536, N=1024, K=512) -> g_hs  (+bar reset)
        dim3 grid(H_ / 128, (B_ * T_) / 128);
        gemm_tf32_kernel<<<grid, 256, GSTAGE * 3 * 4>>>(X, W_xh, b_h, hs_ptr,
                                                        B_ * T_, H_, E_, 1);
    }

    // recurrence (writes h_final into out tail at t=T-1)
    rnn_steps_kernel<<<128, 256, 200192>>>(W_hh, out + (size_t)B_ * T_ * V_);

    {   // Y = hs @ W_hy + b_y  (M=65536, N=512, K=1024) -> out
        dim3 grid(V_ / 128, (B_ * T_) / 128);
        gemm_tf32_kernel<<<grid, 256, GSTAGE * 3 * 4>>>(hs_ptr, W_hy, b_y, out,
                                                        B_ * T_, V_, H_, 0);
    }
}

// round 7
// speedup vs baseline: 2.4777x; 1.1392x over previous
#include <cuda_runtime.h>
#include <cuda_bf16.h>
#include <math.h>
#include <cstdint>

#define B_ 64
#define T_ 1024
#define E_ 512
#define H_ 1024
#define V_ 512

// ---------------------------------------------------------------------------
// Scratch (static device arrays; no allocation allowed)
// ---------------------------------------------------------------------------
__device__ float g_hs[(size_t)B_ * T_ * H_];                 // xproj (fp32)
__device__ __nv_bfloat16 g_hshi[(size_t)B_ * T_ * H_];       // h split hi
__device__ __nv_bfloat16 g_hslo[(size_t)B_ * T_ * H_];       // h split lo
__device__ __nv_bfloat16 g_Xhi[(size_t)B_ * T_ * E_];
__device__ __nv_bfloat16 g_Xlo[(size_t)B_ * T_ * E_];
__device__ __nv_bfloat16 g_WxhThi[(size_t)H_ * E_];          // [N=H][K=E]
__device__ __nv_bfloat16 g_WxhTlo[(size_t)H_ * E_];
__device__ __nv_bfloat16 g_WhyThi[(size_t)V_ * H_];          // [N=V][K=H]
__device__ __nv_bfloat16 g_WhyTlo[(size_t)V_ * H_];
__device__ unsigned g_bar[4];

// ---------------------------------------------------------------------------
// Legacy MMA helpers (sm_100-base safe; proven in R3)
// ---------------------------------------------------------------------------
#define LDSM4(r0, r1, r2, r3, addr)                                           \
    asm volatile("ldmatrix.sync.aligned.m8n8.x4.shared.b16 {%0,%1,%2,%3}, [%4];" \
                 : "=r"(r0), "=r"(r1), "=r"(r2), "=r"(r3) : "r"(addr))
#define MMA_BF16(d, a0, a1, a2, a3, b0, b1)                                   \
    asm volatile("mma.sync.aligned.m16n8k16.row.col.f32.bf16.bf16.f32 "       \
                 "{%0,%1,%2,%3},{%4,%5,%6,%7},{%8,%9},{%0,%1,%2,%3};"         \
                 : "+f"(d[0]), "+f"(d[1]), "+f"(d[2]), "+f"(d[3])             \
                 : "r"(a0), "r"(a1), "r"(a2), "r"(a3), "r"(b0), "r"(b1))
#define CP_COMMIT() asm volatile("cp.async.commit_group;" ::: "memory")

// ---------------------------------------------------------------------------
// Split kernels
// ---------------------------------------------------------------------------
__global__ void split_kernel(const float* __restrict__ src,
                             __nv_bfloat16* __restrict__ hi,
                             __nv_bfloat16* __restrict__ lo, int n4)
{
    int i = blockIdx.x * blockDim.x + threadIdx.x;
    if (blockIdx.x == 0 && threadIdx.x < 4) g_bar[threadIdx.x] = 0u;
    if (i >= n4) return;
    float4 v = ((const float4*)src)[i];
    __nv_bfloat162 h0, h1, l0, l1;
    h0.x = __float2bfloat16(v.x); h0.y = __float2bfloat16(v.y);
    h1.x = __float2bfloat16(v.z); h1.y = __float2bfloat16(v.w);
    l0.x = __float2bfloat16(v.x - __bfloat162float(h0.x));
    l0.y = __float2bfloat16(v.y - __bfloat162float(h0.y));
    l1.x = __float2bfloat16(v.z - __bfloat162float(h1.x));
    l1.y = __float2bfloat16(v.w - __bfloat162float(h1.y));
    ((__nv_bfloat162*)hi)[2 * i]     = h0;
    ((__nv_bfloat162*)hi)[2 * i + 1] = h1;
    ((__nv_bfloat162*)lo)[2 * i]     = l0;
    ((__nv_bfloat162*)lo)[2 * i + 1] = l1;
}

// W [K][N] fp32  ->  hiT/loT [N][K] bf16
__global__ void tsplit_kernel(const float* __restrict__ W,
                              __nv_bfloat16* __restrict__ hiT,
                              __nv_bfloat16* __restrict__ loT, int K, int N)
{
    __shared__ float tile[32][33];
    int tx = threadIdx.x;
    int n0 = blockIdx.x * 32;
    int k0 = blockIdx.y * 32;
    for (int j = threadIdx.y; j < 32; j += 8)
        tile[j][tx] = W[(size_t)(k0 + j) * N + n0 + tx];
    __syncthreads();
    for (int j = threadIdx.y; j < 32; j += 8) {
        float v = tile[tx][j];
        __nv_bfloat16 h = __float2bfloat16(v);
        size_t o = (size_t)(n0 + j) * K + k0 + tx;
        hiT[o] = h;
        loT[o] = __float2bfloat16(v - __bfloat162float(h));
    }
}

// ---------------------------------------------------------------------------
// bf16 3-term GEMM (legacy m16n8k16): C[M,N] = (Ahi+Alo) @ (BhiT+BloT)^T + bias
// CTA 128x128, K-chunk 64, 8 warps each 64x32, double-buffered cp.async.
// Smem rows stride 72 halves (ldmatrix + direct-LDS conflict-free).
// ---------------------------------------------------------------------------
#define ASTR 72
#define MAT_HALVES (128 * ASTR)             // 9216 halves = 18432 bytes
#define STAGE_HALVES (4 * MAT_HALVES)       // 36864 halves = 73728 bytes
#define STAGE_BYTES (STAGE_HALVES * 2)
#define GEMM_SMEM (2 * STAGE_BYTES)         // 147456 bytes

__device__ __forceinline__ void load_stage_b(
    uint32_t base, int tid,
    const __nv_bfloat16* Ahi, const __nv_bfloat16* Alo,
    const __nv_bfloat16* BhiT, const __nv_bfloat16* BloT,
    int K, int arow0, int brow0, int k0)
{
#pragma unroll
    for (int i = 0; i < 4; ++i) {
        int idx = i * 256 + tid;
        int row = idx >> 3;
        int q   = idx & 7;
        uint32_t d = base + (uint32_t)(row * 144 + q * 16);
        const __nv_bfloat16* p0 = Ahi + (size_t)(arow0 + row) * K + k0 + q * 8;
        asm volatile("cp.async.cg.shared.global [%0], [%1], 16;"
                     :: "r"(d), "l"(p0));
        const __nv_bfloat16* p1 = Alo + (size_t)(arow0 + row) * K + k0 + q * 8;
        asm volatile("cp.async.cg.shared.global [%0], [%1], 16;"
                     :: "r"(d + 18432u), "l"(p1));
        const __nv_bfloat16* p2 = BhiT + (size_t)(brow0 + row) * K + k0 + q * 8;
        asm volatile("cp.async.cg.shared.global [%0], [%1], 16;"
                     :: "r"(d + 36864u), "l"(p2));
        const __nv_bfloat16* p3 = BloT + (size_t)(brow0 + row) * K + k0 + q * 8;
        asm volatile("cp.async.cg.shared.global [%0], [%1], 16;"
                     :: "r"(d + 55296u), "l"(p3));
    }
}

__global__ __launch_bounds__(256) void gemm_bf16_kernel(
    const __nv_bfloat16* __restrict__ Ahi, const __nv_bfloat16* __restrict__ Alo,
    const __nv_bfloat16* __restrict__ BhiT, const __nv_bfloat16* __restrict__ BloT,
    const float* __restrict__ bias, float* __restrict__ C,
    int M, int N, int K)
{
    extern __shared__ __nv_bfloat16 smh[];
    const uint32_t sbase = (uint32_t)__cvta_generic_to_shared(smh);

    const int tid  = threadIdx.x;
    const int lane = tid & 31;
    const int warp = tid >> 5;
    const int wm   = warp & 1;        // 2 m-halves of 64
    const int wn   = warp >> 1;       // 4 n-cols of 32
    const int g    = lane >> 2;
    const int tq   = lane & 3;
    const int bx = blockIdx.x;
    const int by = blockIdx.y;
    const int KT = K >> 6;
    const int arow0 = by * 128;
    const int brow0 = bx * 128;

    // ldmatrix lane address pieces (same mapping as the proven recurrence)
    const int sub  = lane >> 3;
    const int lrow = ((sub & 1) << 3) + (lane & 7);
    const int lkof = (sub >> 1) << 3;          // halves
    // byte offset of this lane's A ldmatrix base within a stage (mt=0, k16=0)
    const uint32_t a_lane_off = (uint32_t)(((wm * 64 + lrow) * ASTR + lkof) * 2);

    float acc[4][4][4];
#pragma unroll
    for (int i = 0; i < 4; ++i)
#pragma unroll
        for (int j = 0; j < 4; ++j)
#pragma unroll
            for (int r = 0; r < 4; ++r) acc[i][j][r] = 0.f;

    load_stage_b(sbase, tid, Ahi, Alo, BhiT, BloT, K, arow0, brow0, 0);
    CP_COMMIT();
    if (KT > 1) {
        load_stage_b(sbase + STAGE_BYTES, tid, Ahi, Alo, BhiT, BloT, K,
                     arow0, brow0, 64);
        CP_COMMIT();
    }

    for (int kt = 0; kt < KT; ++kt) {
        const int s = kt & 1;
        if (kt + 1 < KT) {
            asm volatile("cp.async.wait_group 1;" ::: "memory");
        } else {
            asm volatile("cp.async.wait_group 0;" ::: "memory");
        }
        __syncthreads();

        const uint32_t stb = sbase + (uint32_t)s * STAGE_BYTES;
        const __nv_bfloat16* stg = smh + (size_t)s * STAGE_HALVES;
        const __nv_bfloat16* bhi_s = stg + 2 * MAT_HALVES;
        const __nv_bfloat16* blo_s = stg + 3 * MAT_HALVES;

#pragma unroll
        for (int k16 = 0; k16 < 4; ++k16) {
            // A fragments (hi & lo) for 4 m-tiles
            unsigned ahi[4][4], alo[4][4];
#pragma unroll
            for (int mt = 0; mt < 4; ++mt) {
                uint32_t aaddr = stb + a_lane_off
                               + (uint32_t)(mt * 16 * ASTR * 2) + (uint32_t)(k16 * 32);
                LDSM4(ahi[mt][0], ahi[mt][1], ahi[mt][2], ahi[mt][3], aaddr);
                LDSM4(alo[mt][0], alo[mt][1], alo[mt][2], alo[mt][3],
                      aaddr + 18432u);
            }
            // B fragments for 4 n-tiles (direct LDS, conflict-free)
            unsigned bh[4][2], bl[4][2];
#pragma unroll
            for (int nt = 0; nt < 4; ++nt) {
                int n = wn * 32 + nt * 8 + g;
                const unsigned* bph = (const unsigned*)(bhi_s + n * ASTR + k16 * 16);
                const unsigned* bpl = (const unsigned*)(blo_s + n * ASTR + k16 * 16);
                bh[nt][0] = bph[tq];
                bh[nt][1] = bph[tq + 4];
                bl[nt][0] = bpl[tq];
                bl[nt][1] = bpl[tq + 4];
            }
#pragma unroll
            for (int mt = 0; mt < 4; ++mt)
#pragma unroll
                for (int nt = 0; nt < 4; ++nt) {
                    MMA_BF16(acc[mt][nt], ahi[mt][0], ahi[mt][1], ahi[mt][2],
                             ahi[mt][3], bh[nt][0], bh[nt][1]);
                    MMA_BF16(acc[mt][nt], ahi[mt][0], ahi[mt][1], ahi[mt][2],
                             ahi[mt][3], bl[nt][0], bl[nt][1]);
                    MMA_BF16(acc[mt][nt], alo[mt][0], alo[mt][1], alo[mt][2],
                             alo[mt][3], bh[nt][0], bh[nt][1]);
                }
        }

        __syncthreads();
        if (kt + 2 < KT) {
            load_stage_b(stb, tid, Ahi, Alo, BhiT, BloT, K, arow0, brow0,
                         (kt + 2) << 6);
            CP_COMMIT();
        }
    }

    // Epilogue: bias add + fp32 stores (c0,c1 -> row, 2tq; c2,c3 -> row+8)
#pragma unroll
    for (int mt = 0; mt < 4; ++mt) {
        int row0 = by * 128 + wm * 64 + mt * 16 + g;
#pragma unroll
        for (int nt = 0; nt < 4; ++nt) {
            int col = bx * 128 + wn * 32 + nt * 8 + 2 * tq;
            float b0 = bias[col];
            float b1 = bias[col + 1];
            float2 v0 = make_float2(acc[mt][nt][0] + b0, acc[mt][nt][1] + b1);
            float2 v1 = make_float2(acc[mt][nt][2] + b0, acc[mt][nt][3] + b1);
            *(float2*)(&C[(size_t)row0 * N + col])       = v0;
            *(float2*)(&C[(size_t)(row0 + 8) * N + col]) = v1;
        }
    }
}

// ---------------------------------------------------------------------------
// Persistent recurrence kernel (R3-proven logic): 128 CTAs = 4 row-groups x
// 32 column slices; W_hh split resident in smem; h staged pre-split per step;
// writes h splits to g_hshi/g_hslo[b][t][h] for gemmB, h_final to out tail.
// ---------------------------------------------------------------------------
__global__ __launch_bounds__(256) void rnn_steps_kernel(
    const float* __restrict__ W_hh, float* __restrict__ out_hf)
{
    extern __shared__ char smc[];
    __nv_bfloat16* Whi = (__nv_bfloat16*)smc;          // [32][1032]
    __nv_bfloat16* Wlo = Whi + 32 * 1032;
    __nv_bfloat16* Hhi = Wlo + 32 * 1032;              // [16][1032]
    __nv_bfloat16* Hlo = Hhi + 16 * 1032;
    float*         red = (float*)(Hlo + 16 * 1032);    // [16][32]

    const int tid  = threadIdx.x;
    const int lane = tid & 31;
    const int warp = tid >> 5;
    const int cc   = blockIdx.x & 31;
    const int rb   = blockIdx.x >> 5;
    const int n0   = cc * 32;
    const int b0   = rb * 16;
    const int g    = lane >> 2;
    const int tq   = lane & 3;
    const int ntile = warp & 3;
    const int khalf = (warp >> 2) << 9;
    const int col   = ntile * 8 + 2 * tq;

    for (int idx = tid; idx < 32768; idx += 256) {
        int n = idx & 31;
        int k = idx >> 5;
        float w = W_hh[(size_t)k * H_ + n0 + n];
        __nv_bfloat16 hi = __float2bfloat16(w);
        float lo = w - __bfloat162float(hi);
        Whi[n * 1032 + k] = hi;
        Wlo[n * 1032 + k] = __float2bfloat16(lo);
    }

    const int sub  = lane >> 3;
    const int lrow = ((sub & 1) << 3) + (lane & 7);
    const int lkof = (sub >> 1) << 3;
    unsigned abase_hi = (unsigned)__cvta_generic_to_shared(
        Hhi + lrow * 1032 + khalf + lkof);
    unsigned abase_lo = (unsigned)__cvta_generic_to_shared(
        Hlo + lrow * 1032 + khalf + lkof);

    const unsigned* bhiw = (const unsigned*)(Whi + (size_t)(ntile * 8 + g) * 1032);
    const unsigned* blow = (const unsigned*)(Wlo + (size_t)(ntile * 8 + g) * 1032);

    volatile unsigned* barp = (volatile unsigned*)&g_bar[rb];
    __syncthreads();

    for (int t = 0; t < T_; ++t) {
        float2 xp0, xp1;
        size_t xbase0 = ((size_t)(b0 + g) * T_ + t) * H_ + n0 + col;
        size_t xbase1 = xbase0 + (size_t)8 * T_ * H_;
        if (warp < 4) {
            xp0 = __ldcg((const float2*)(g_hs + xbase0));
            xp1 = __ldcg((const float2*)(g_hs + xbase1));
        }

        float v00 = 0.f, v01 = 0.f, v10 = 0.f, v11 = 0.f;
        if (t > 0) {
            const __nv_bfloat16* shh = g_hshi + ((size_t)b0 * T_ + (t - 1)) * H_;
            const __nv_bfloat16* shl = g_hslo + ((size_t)b0 * T_ + (t - 1)) * H_;
#pragma unroll
            for (int j = 0; j < 8; ++j) {
                int idx = j * 256 + tid;
                int r = idx >> 7;
                int c = (idx & 127) << 3;
                *(uint4*)(Hhi + r * 1032 + c) =
                    __ldcg((const uint4*)(shh + (size_t)r * T_ * H_ + c));
                *(uint4*)(Hlo + r * 1032 + c) =
                    __ldcg((const uint4*)(shl + (size_t)r * T_ * H_ + c));
            }
            __syncthreads();

            float hh[4] = {0.f, 0.f, 0.f, 0.f};
            float hl[4] = {0.f, 0.f, 0.f, 0.f};
            float lh[4] = {0.f, 0.f, 0.f, 0.f};
            unsigned ah = abase_hi;
            unsigned al = abase_lo;
#pragma unroll 4
            for (int c = 0; c < 32; ++c) {
                unsigned a0, a1, a2, a3, l0, l1, l2, l3;
                LDSM4(a0, a1, a2, a3, ah);
                LDSM4(l0, l1, l2, l3, al);
                ah += 32; al += 32;
                int widx = ((khalf + (c << 4)) >> 1) + tq;
                unsigned bh0 = bhiw[widx];
                unsigned bh1 = bhiw[widx + 4];
                unsigned bl0 = blow[widx];
                unsigned bl1 = blow[widx + 4];
                MMA_BF16(hh, a0, a1, a2, a3, bh0, bh1);
                MMA_BF16(hl, a0, a1, a2, a3, bl0, bl1);
                MMA_BF16(lh, l0, l1, l2, l3, bh0, bh1);
            }
            float s0 = hh[0] + hl[0] + lh[0];
            float s1 = hh[1] + hl[1] + lh[1];
            float s2 = hh[2] + hl[2] + lh[2];
            float s3 = hh[3] + hl[3] + lh[3];
            if (warp >= 4) {
                *(float2*)(red + g * 32 + col)       = make_float2(s0, s1);
                *(float2*)(red + (g + 8) * 32 + col) = make_float2(s2, s3);
            }
            __syncthreads();
            if (warp < 4) {
                float2 r0 = *(float2*)(red + g * 32 + col);
                float2 r1 = *(float2*)(red + (g + 8) * 32 + col);
                v00 = s0 + r0.x + xp0.x;
                v01 = s1 + r0.y + xp0.y;
                v10 = s2 + r1.x + xp1.x;
                v11 = s3 + r1.y + xp1.y;
            }
        } else {
            if (warp < 4) {
                v00 = xp0.x; v01 = xp0.y; v10 = xp1.x; v11 = xp1.y;
            }
        }

        if (warp < 4) {
            float o00 = tanhf(v00);
            float o01 = tanhf(v01);
            float o10 = tanhf(v10);
            float o11 = tanhf(v11);

            __nv_bfloat16 h00 = __float2bfloat16(o00);
            __nv_bfloat16 h01 = __float2bfloat16(o01);
            __nv_bfloat16 h10 = __float2bfloat16(o10);
            __nv_bfloat16 h11 = __float2bfloat16(o11);
            __nv_bfloat162 phi0; phi0.x = h00; phi0.y = h01;
            __nv_bfloat162 phi1; phi1.x = h10; phi1.y = h11;
            __nv_bfloat162 plo0;
            plo0.x = __float2bfloat16(o00 - __bfloat162float(h00));
            plo0.y = __float2bfloat16(o01 - __bfloat162float(h01));
            __nv_bfloat162 plo1;
            plo1.x = __float2bfloat16(o10 - __bfloat162float(h10));
            plo1.y = __float2bfloat16(o11 - __bfloat162float(h11));

            size_t d0 = ((size_t)(b0 + g) * T_ + t) * H_ + n0 + col;
            size_t d1 = d0 + (size_t)8 * T_ * H_;
            *(__nv_bfloat162*)(g_hshi + d0) = phi0;
            *(__nv_bfloat162*)(g_hshi + d1) = phi1;
            *(__nv_bfloat162*)(g_hslo + d0) = plo0;
            *(__nv_bfloat162*)(g_hslo + d1) = plo1;

            if (t == T_ - 1) {
                size_t f0 = (size_t)(b0 + g) * H_ + n0 + col;
                *(float2*)(out_hf + f0)                  = make_float2(o00, o01);
                *(float2*)(out_hf + f0 + (size_t)8 * H_) = make_float2(o10, o11);
            }
        }

        __threadfence();
        __syncthreads();
        if (tid == 0) {
            atomicAdd(&g_bar[rb], 1u);
            unsigned target = 32u * (unsigned)(t + 1);
            while (*barp < target) { }
        }
        __syncthreads();
    }
}

extern "C" void kernel_launch(void* const* d_in, const int* in_sizes, int n_in,
                              void* d_out, int out_size)
{
    const float* X    = (const float*)d_in[0];
    const float* W_xh = (const float*)d_in[1];
    const float* b_h  = (const float*)d_in[2];
    const float* W_hh = (const float*)d_in[3];
    const float* W_hy = (const float*)d_in[4];
    const float* b_y  = (const float*)d_in[5];
    float* out = (float*)d_out;

    float* hs_ptr = 0;
    __nv_bfloat16* xhi = 0;
    __nv_bfloat16* xlo = 0;
    __nv_bfloat16* hshi = 0;
    __nv_bfloat16* hslo = 0;
    __nv_bfloat16* wxh_hi = 0;
    __nv_bfloat16* wxh_lo = 0;
    __nv_bfloat16* why_hi = 0;
    __nv_bfloat16* why_lo = 0;
    cudaGetSymbolAddress((void**)&hs_ptr, g_hs);
    cudaGetSymbolAddress((void**)&xhi, g_Xhi);
    cudaGetSymbolAddress((void**)&xlo, g_Xlo);
    cudaGetSymbolAddress((void**)&hshi, g_hshi);
    cudaGetSymbolAddress((void**)&hslo, g_hslo);
    cudaGetSymbolAddress((void**)&wxh_hi, g_WxhThi);
    cudaGetSymbolAddress((void**)&wxh_lo, g_WxhTlo);
    cudaGetSymbolAddress((void**)&why_hi, g_WhyThi);
    cudaGetSymbolAddress((void**)&why_lo, g_WhyTlo);

    cudaFuncSetAttribute(rnn_steps_kernel,
                         cudaFuncAttributeMaxDynamicSharedMemorySize, 200192);
    cudaFuncSetAttribute(gemm_bf16_kernel,
                         cudaFuncAttributeMaxDynamicSharedMemorySize, GEMM_SMEM);

    // 0) split X (also resets barrier counters)
    split_kernel<<<(B_ * T_ * E_ / 4 + 255) / 256, 256>>>(X, xhi, xlo,
                                                          B_ * T_ * E_ / 4);
    // 1) transpose-split weights
    tsplit_kernel<<<dim3(H_ / 32, E_ / 32), dim3(32, 8)>>>(W_xh, wxh_hi, wxh_lo,
                                                           E_, H_);
    tsplit_kernel<<<dim3(V_ / 32, H_ / 32), dim3(32, 8)>>>(W_hy, why_hi, why_lo,
                                                           H_, V_);
    // 2) xproj = X @ W_xh + b_h -> g_hs (fp32)
    gemm_bf16_kernel<<<dim3(H_ / 128, (B_ * T_) / 128), 256, GEMM_SMEM>>>(
        xhi, xlo, wxh_hi, wxh_lo, b_h, hs_ptr, B_ * T_, H_, E_);
    // 3) recurrence (writes h splits + h_final)
    rnn_steps_kernel<<<128, 256, 200192>>>(W_hh, out + (size_t)B_ * T_ * V_);
    // 4) Y = hs @ W_hy + b_y -> out
    gemm_bf16_kernel<<<dim3(V_ / 128, (B_ * T_) / 128), 256, GEMM_SMEM>>>(
        hshi, hslo, why_hi, why_lo, b_y, out, B_ * T_, V_, H_);
}